// round 16
// baseline (speedup 1.0000x reference)
#include <cuda_runtime.h>
#include <math.h>
#include <stdint.h>

#define BH 512

// ------------------------------- scratch -----------------------------------
__device__ float g_bufA[16777216];
__device__ float g_bufB[16777216];
__device__ float g_bufT[4194304];
__device__ float g_bufZ[8388608];
__device__ float g_V[37748736];      // [36][512][2048]
__device__ float g_M[37748736];      // [36][Cout][2048]

// 3xTF32 U weights in mma-fragment layout (tf32-rounded fp32 + residual)
__device__ float g_uh1[4718592],  g_ul1[4718592];    // conv1  [36][256->512]
__device__ float g_uh2[9437184],  g_ul2[9437184];    // conv2
__device__ float g_uh3[4718592],  g_ul3[4718592];    // conv3
__device__ float g_uhE[37748736], g_ulE[37748736];   // enc res x16
__device__ float g_uhD0[4718592], g_ulD0[4718592];   // dec c0
__device__ float g_uhD1[4718592], g_ulD1[4718592];   // dec c1
__device__ float g_uhDr[37748736], g_ulDr[37748736]; // dec res x16

__device__ float g_pwE2[1048576];
__device__ float g_pwDr2[1048576];
__device__ float g_cbT[262144];
__device__ float g_cnorm[1024];
__device__ float g_znorm[32768];
__device__ unsigned long long g_bestkey[32768];
__device__ float g_bnscale[512];
__device__ float g_bnshift[512];
__device__ float g_vqsum;
__device__ float g_reconsum;

// ---------------------------- helpers --------------------------------------
__device__ __forceinline__ float warpReduceSum(float v) {
#pragma unroll
    for (int s = 16; s > 0; s >>= 1) v += __shfl_down_sync(0xffffffffu, v, s);
    return v;
}
__device__ __forceinline__ uint32_t to_tf32(float v) {
    uint32_t u;
    asm("cvt.rna.tf32.f32 %0, %1;" : "=r"(u) : "f"(v));
    return u;
}
__device__ __forceinline__ void mma_tf(float* c, const uint4& a, uint32_t b0, uint32_t b1) {
    asm volatile(
        "mma.sync.aligned.m16n8k8.row.col.f32.tf32.tf32.f32 "
        "{%0,%1,%2,%3}, {%4,%5,%6,%7}, {%8,%9}, {%0,%1,%2,%3};"
        : "+f"(c[0]), "+f"(c[1]), "+f"(c[2]), "+f"(c[3])
        : "r"(a.x), "r"(a.y), "r"(a.z), "r"(a.w), "r"(b0), "r"(b1));
}

// ------------------------------ pack kernels -------------------------------
__global__ void pack1x1_k(const float* __restrict__ src, float* __restrict__ dst,
                          int nblk, int Cin, int Cout) {
    long long total = (long long)nblk * Cout * Cin;
    for (long long i = (long long)blockIdx.x * blockDim.x + threadIdx.x; i < total;
         i += (long long)gridDim.x * blockDim.x) {
        int ci = (int)(i % Cin);
        long long t = i / Cin;
        int co = (int)(t % Cout);
        int blk = (int)(t / Cout);
        dst[((long long)blk * Cin + ci) * Cout + co] = src[i];
    }
}

// F(4x4) weight transform -> 2-split tf32 in mma fragment layout.
// Fragment index for element (co, ci) of plane p:
//   lane = (co&7)*4 + (ci&3); reg = ((co>>3)&1) | (((ci>>2)&1)<<1)
//   idx = ((img*8 + mt)*K8 + kc8)*128 + lane*4 + reg, img=(blk*36+p)*coC+coc
__global__ void wtrans4f_k(const float* __restrict__ w, float* __restrict__ Uh,
                           float* __restrict__ Ul, int nblk, int Cin, int Cout) {
    long long total = (long long)nblk * Cout * Cin;
    long long idx = (long long)blockIdx.x * blockDim.x + threadIdx.x;
    if (idx >= total) return;
    int ci = (int)(idx % Cin);
    long long rest = idx / Cin;
    int co = (int)(rest % Cout);
    int blk = (int)(rest / Cout);
    const float* g = w + idx * 9;
    float q[6][3];
#pragma unroll
    for (int j = 0; j < 3; j++) {
        float g0 = g[j], g1 = g[3 + j], g2 = g[6 + j];
        q[0][j] = 0.25f * g0;
        q[1][j] = (-g0 - g1 - g2) * (1.f / 6.f);
        q[2][j] = (-g0 + g1 - g2) * (1.f / 6.f);
        q[3][j] = g0 * (1.f / 24.f) + g1 * (1.f / 12.f) + g2 * (1.f / 6.f);
        q[4][j] = g0 * (1.f / 24.f) - g1 * (1.f / 12.f) + g2 * (1.f / 6.f);
        q[5][j] = g2;
    }
    const int coC = Cout >> 7, K8 = Cin >> 3;
    const int coc = co >> 7, mt = (co >> 4) & 7, rh = (co >> 3) & 1, gr = co & 7;
    const int kc8 = ci >> 3, ch = (ci >> 2) & 1, tg = ci & 3;
    const int lane = gr * 4 + tg, reg = rh | (ch << 1);
#pragma unroll
    for (int i = 0; i < 6; i++) {
        float t0 = q[i][0], t1 = q[i][1], t2 = q[i][2];
        float u[6];
        u[0] = 0.25f * t0;
        u[1] = (-t0 - t1 - t2) * (1.f / 6.f);
        u[2] = (-t0 + t1 - t2) * (1.f / 6.f);
        u[3] = t0 * (1.f / 24.f) + t1 * (1.f / 12.f) + t2 * (1.f / 6.f);
        u[4] = t0 * (1.f / 24.f) - t1 * (1.f / 12.f) + t2 * (1.f / 6.f);
        u[5] = t2;
#pragma unroll
        for (int j = 0; j < 6; j++) {
            int p = i * 6 + j;
            size_t img = ((size_t)blk * 36 + p) * coC + coc;
            size_t a = ((img * 8 + mt) * K8 + kc8) * 128 + lane * 4 + reg;
            float v = u[j];
            float hf = __uint_as_float(to_tf32(v));
            float lf = __uint_as_float(to_tf32(v - hf));
            Uh[a] = hf;
            Ul[a] = lf;
        }
    }
}

__global__ void packT_k(const float* __restrict__ src, float* __restrict__ dst) {
    int i = blockIdx.x * blockDim.x + threadIdx.x;
    if (i < 262144) {
        int d = i & 255, k = i >> 8;
        dst[d * 1024 + k] = src[i];
    }
}
__global__ void init_k(unsigned long long* bestkey, float* vqsum, float* reconsum) {
    int i = blockIdx.x * blockDim.x + threadIdx.x;
    if (i < 32768) bestkey[i] = 0xFFFFFFFFFFFFFFFFull;
    if (i == 0) { *vqsum = 0.f; *reconsum = 0.f; }
}
__global__ void cnorm_k(const float* __restrict__ cb, float* __restrict__ cn) {
    int k = blockIdx.x;
    float v = cb[k * 256 + threadIdx.x];
    float p = warpReduceSum(v * v);
    __shared__ float sh[8];
    if ((threadIdx.x & 31) == 0) sh[threadIdx.x >> 5] = p;
    __syncthreads();
    if (threadIdx.x == 0) {
        float t = 0.f;
#pragma unroll
        for (int i = 0; i < 8; i++) t += sh[i];
        cn[k] = t;
    }
}
__global__ void znorm_k(const float* __restrict__ z, float* __restrict__ zn) {
    int n = blockIdx.x * blockDim.x + threadIdx.x;
    if (n >= 32768) return;
    int b = n >> 12, rem = n & 4095;
    const float* zp = z + (((size_t)b * 256) << 12) + rem;
    float s = 0.f;
#pragma unroll 8
    for (int d = 0; d < 256; d++) {
        float v = zp[(size_t)d << 12];
        s = fmaf(v, v, s);
    }
    zn[n] = s;
}

// ------------------------------ conv0 (4x4 s2) ------------------------------
__global__ void conv0_k(const float* __restrict__ x, const float* __restrict__ w,
                        const float* __restrict__ bias, float* __restrict__ out) {
    int idx = blockIdx.x * blockDim.x + threadIdx.x;
    if (idx >= 8388608) return;
    int ox = idx & 63, oy = (idx >> 6) & 63, co = (idx >> 12) & 255, b = idx >> 20;
    float acc = bias[co];
    const float* wc = w + co * 48;
#pragma unroll
    for (int c = 0; c < 3; c++) {
        const float* xp = x + (size_t)(b * 3 + c) * 16384;
#pragma unroll
        for (int ky = 0; ky < 4; ky++) {
            int iy = oy * 2 - 1 + ky;
            if (iy < 0 || iy >= 128) continue;
#pragma unroll
            for (int kx = 0; kx < 4; kx++) {
                int ix = ox * 2 - 1 + kx;
                if (ix < 0 || ix >= 128) continue;
                acc = fmaf(xp[iy * 128 + ix], wc[c * 16 + ky * 4 + kx], acc);
            }
        }
    }
    out[idx] = acc;
}

// ------------------------------- batchnorm ----------------------------------
__global__ void bn_stats_k(const float* __restrict__ buf, const float* __restrict__ g,
                           const float* __restrict__ bb, int C,
                           float* __restrict__ scale, float* __restrict__ shift) {
    int c = blockIdx.x;
    int tid = threadIdx.x;
    double s = 0.0, s2 = 0.0;
    for (int t = tid; t < 8 * 4096; t += 256) {
        int b = t >> 12, off = t & 4095;
        float v = buf[(((size_t)b * C + c) << 12) + off];
        s += (double)v; s2 += (double)v * v;
    }
    __shared__ double sh[256], sh2[256];
    sh[tid] = s; sh2[tid] = s2;
    __syncthreads();
    for (int st = 128; st; st >>= 1) {
        if (tid < st) { sh[tid] += sh[tid + st]; sh2[tid] += sh2[tid + st]; }
        __syncthreads();
    }
    if (tid == 0) {
        double m = sh[0] / 32768.0;
        double v = sh2[0] / 32768.0 - m * m;
        double sc = (double)g[c] / sqrt(v + 1e-5);
        scale[c] = (float)sc;
        shift[c] = (float)((double)bb[c] - m * sc);
    }
}
__global__ void bn_apply_k(float* __restrict__ buf, const float* __restrict__ scale,
                           const float* __restrict__ shift, int C, int total) {
    int i = blockIdx.x * blockDim.x + threadIdx.x;
    if (i >= total) return;
    int c = (i >> 12) % C;
    buf[i] = fmaxf(fmaf(buf[i], scale[c], shift[c]), 0.f);
}
__global__ void relu_ip_k(float* __restrict__ buf, int total) {
    int i = blockIdx.x * blockDim.x + threadIdx.x;
    if (i < total) buf[i] = fmaxf(buf[i], 0.f);
}

// ---------------------- F(4x4): input transform -----------------------------
template <bool RELU>
__global__ void win4_in_k(const float* __restrict__ in, float* __restrict__ V, int Cin) {
    int idx = blockIdx.x * 256 + threadIdx.x;
    if (idx >= (Cin << 11)) return;
    int tile = idx & 2047, ci = idx >> 11;
    int b = tile >> 8, t = tile & 255, ty = t >> 4, tx = t & 15;
    const float* src = in + (((size_t)b * Cin + ci) << 12);
    const int iy0 = 4 * ty - 1, ix0 = 4 * tx - 1;
    float d[6][6];
#pragma unroll
    for (int i = 0; i < 6; i++) {
        int iy = iy0 + i;
        bool yok = (iy >= 0 && iy < 64);
#pragma unroll
        for (int j = 0; j < 6; j++) {
            int ix = ix0 + j;
            float v = (yok && ix >= 0 && ix < 64) ? src[iy * 64 + ix] : 0.f;
            if (RELU) v = fmaxf(v, 0.f);
            d[i][j] = v;
        }
    }
    float w[6][6];
#pragma unroll
    for (int j = 0; j < 6; j++) {
        w[0][j] = 4.f * d[0][j] - 5.f * d[2][j] + d[4][j];
        w[1][j] = -4.f * d[1][j] - 4.f * d[2][j] + d[3][j] + d[4][j];
        w[2][j] = 4.f * d[1][j] - 4.f * d[2][j] - d[3][j] + d[4][j];
        w[3][j] = -2.f * d[1][j] - d[2][j] + 2.f * d[3][j] + d[4][j];
        w[4][j] = 2.f * d[1][j] - d[2][j] - 2.f * d[3][j] + d[4][j];
        w[5][j] = 4.f * d[1][j] - 5.f * d[3][j] + d[5][j];
    }
#pragma unroll
    for (int i = 0; i < 6; i++) {
        float v0 = 4.f * w[i][0] - 5.f * w[i][2] + w[i][4];
        float v1 = -4.f * w[i][1] - 4.f * w[i][2] + w[i][3] + w[i][4];
        float v2 = 4.f * w[i][1] - 4.f * w[i][2] - w[i][3] + w[i][4];
        float v3 = -2.f * w[i][1] - w[i][2] + 2.f * w[i][3] + w[i][4];
        float v4 = 2.f * w[i][1] - w[i][2] - 2.f * w[i][3] + w[i][4];
        float v5 = 4.f * w[i][1] - 5.f * w[i][3] + w[i][5];
        size_t pl = (size_t)512 * 2048;
        size_t base = ((size_t)(i * 6) * 512 + ci) * 2048 + tile;
        V[base]          = v0;
        V[base + pl]     = v1;
        V[base + 2 * pl] = v2;
        V[base + 3 * pl] = v3;
        V[base + 4 * pl] = v4;
        V[base + 5 * pl] = v5;
    }
}

// -------------- 3xTF32 mma.sync Winograd batched GEMM -----------------------
// M[r][co][tile] = sum_ci U[r][ci][co]*V[r][ci][tile], fp32-equivalent.
// CTA: 128 co x 128 tiles; 8 warps, warp tile 32x64; K chunks of 32.
__global__ void __launch_bounds__(256)
win_gemm_tf_k(const float* __restrict__ Uh, const float* __restrict__ Ul,
              const float* __restrict__ V, float* __restrict__ Mo,
              int Cin, int Cout) {
    extern __shared__ __align__(16) float dyn[];
    float* As0 = dyn;                 // 4096 floats (frag layout)
    float* As1 = dyn + 4096;
    float* Bs0 = dyn + 8192;          // 32 x 136
    float* Bs1 = dyn + 8192 + 4352;

    const int coC = Cout >> 7;
    const int K8 = Cin >> 3;
    const int r = blockIdx.x / coC;
    const int coc = blockIdx.x - r * coC;
    const int tile0 = blockIdx.y << 7;
    const int tid = threadIdx.x;
    const int lane = tid & 31, wid = tid >> 5;
    const int wm = wid >> 1, wn = wid & 1;
    const int gr = lane >> 2, tg = lane & 3;

    float c[2][8][4];
#pragma unroll
    for (int i = 0; i < 2; i++)
#pragma unroll
        for (int j = 0; j < 8; j++)
#pragma unroll
            for (int k = 0; k < 4; k++) c[i][j][k] = 0.f;

    const float4* Ug0 = (const float4*)(Uh + ((size_t)(r * coC + coc) * 8) * K8 * 128);
    const float4* Ug1 = (const float4*)(Ul + ((size_t)(r * coC + coc) * 8) * K8 * 128);
    const float* Vr = V + ((size_t)r * 512) * 2048 + tile0;
    const int rowF4 = K8 * 32;        // float4s per mt row

    const int nChunks = Cin >> 5;
    for (int kc = 0; kc < nChunks; kc++) {
        // A: straight frag-ordered copy (1024 float4 per split)
#pragma unroll
        for (int i = 0; i < 4; i++) {
            int f4 = tid + (i << 8);
            int mt = f4 >> 7, j = f4 & 127;
            size_t gidx = (size_t)mt * rowF4 + kc * 128 + j;
            ((float4*)As0)[f4] = Ug0[gidx];
            ((float4*)As1)[f4] = Ug1[gidx];
        }
        // B: read fp32 V, split to tf32 h/l, smem stride 136 (conflict-free frags)
#pragma unroll
        for (int i = 0; i < 16; i++) {
            int e = tid + (i << 8);
            int k = e >> 7, n = e & 127;
            float v = Vr[(size_t)(kc * 32 + k) * 2048 + n];
            float hf = __uint_as_float(to_tf32(v));
            float lf = __uint_as_float(to_tf32(v - hf));
            Bs0[k * 136 + n] = hf;
            Bs1[k * 136 + n] = lf;
        }
        __syncthreads();
#pragma unroll
        for (int k8 = 0; k8 < 4; k8++) {
            uint4 ah[2], al[2];
#pragma unroll
            for (int mt = 0; mt < 2; mt++) {
                int f4 = (wm * 2 + mt) * 128 + k8 * 32 + lane;
                ah[mt] = ((const uint4*)As0)[f4];
                al[mt] = ((const uint4*)As1)[f4];
            }
            const float* b0p = Bs0 + (k8 * 8 + tg) * 136 + wn * 64 + gr;
            const float* b1p = Bs1 + (k8 * 8 + tg) * 136 + wn * 64 + gr;
#pragma unroll
            for (int nt = 0; nt < 8; nt++) {
                uint32_t bh0 = __float_as_uint(b0p[nt * 8]);
                uint32_t bh1 = __float_as_uint(b0p[nt * 8 + 4 * 136]);
                uint32_t bl0 = __float_as_uint(b1p[nt * 8]);
                uint32_t bl1 = __float_as_uint(b1p[nt * 8 + 4 * 136]);
#pragma unroll
                for (int mt = 0; mt < 2; mt++) {
                    mma_tf(c[mt][nt], ah[mt], bh0, bh1);
                    mma_tf(c[mt][nt], ah[mt], bl0, bl1);
                    mma_tf(c[mt][nt], al[mt], bh0, bh1);
                }
            }
        }
        __syncthreads();
    }

    // epilogue: C frags -> gmem (float2 pairs, 32B sectors)
#pragma unroll
    for (int mt = 0; mt < 2; mt++) {
        int co = (coc << 7) + wm * 32 + mt * 16 + gr;
        float* base = Mo + ((size_t)r * Cout + co) * 2048 + tile0 + wn * 64;
        float* base8 = base + (size_t)8 * 2048;
#pragma unroll
        for (int nt = 0; nt < 8; nt++) {
            int cc = nt * 8 + tg * 2;
            *(float2*)&base[cc] = make_float2(c[mt][nt][0], c[mt][nt][1]);
            *(float2*)&base8[cc] = make_float2(c[mt][nt][2], c[mt][nt][3]);
        }
    }
}

// ---------------------- F(4x4): inverse transform ---------------------------
template <bool RELU>
__global__ void win4_out_k(const float* __restrict__ M, const float* __restrict__ bias,
                           float* __restrict__ out, int Cout) {
    int idx = blockIdx.x * 256 + threadIdx.x;
    if (idx >= (Cout << 11)) return;
    int tile = idx & 2047, co = idx >> 11;
    float m[6][6];
#pragma unroll
    for (int i = 0; i < 6; i++)
#pragma unroll
        for (int j = 0; j < 6; j++)
            m[i][j] = M[((size_t)(i * 6 + j) * Cout + co) * 2048 + tile];
    float s[4][6];
#pragma unroll
    for (int j = 0; j < 6; j++) {
        s[0][j] = m[0][j] + m[1][j] + m[2][j] + m[3][j] + m[4][j];
        s[1][j] = m[1][j] - m[2][j] + 2.f * (m[3][j] - m[4][j]);
        s[2][j] = m[1][j] + m[2][j] + 4.f * (m[3][j] + m[4][j]);
        s[3][j] = m[1][j] - m[2][j] + 8.f * (m[3][j] - m[4][j]) + m[5][j];
    }
    const float bs = bias[co];
    int b = tile >> 8, t = tile & 255, ty = t >> 4, tx = t & 15;
    float* dst0 = out + (((size_t)b * Cout + co) << 12) + (4 * ty) * 64 + 4 * tx;
#pragma unroll
    for (int i = 0; i < 4; i++) {
        float y0 = s[i][0] + s[i][1] + s[i][2] + s[i][3] + s[i][4] + bs;
        float y1 = s[i][1] - s[i][2] + 2.f * (s[i][3] - s[i][4]) + bs;
        float y2 = s[i][1] + s[i][2] + 4.f * (s[i][3] + s[i][4]) + bs;
        float y3 = s[i][1] - s[i][2] + 8.f * (s[i][3] - s[i][4]) + s[i][5] + bs;
        if (RELU) {
            y0 = fmaxf(y0, 0.f); y1 = fmaxf(y1, 0.f);
            y2 = fmaxf(y2, 0.f); y3 = fmaxf(y3, 0.f);
        }
        float* dst = dst0 + i * 64;
        dst[0] = y0; dst[1] = y1; dst[2] = y2; dst[3] = y3;
    }
}

// --------------------- 1x1 conv + residual add (scalar) ----------------------
__global__ void __launch_bounds__(256)
conv1x1_acc_k(const float* __restrict__ in, const float* __restrict__ wp,
              const float* __restrict__ bias, float* __restrict__ out,
              int Cin, int Cout) {
    const int cout0 = blockIdx.x * 128;
    const int by = blockIdx.y;
    const int b = by >> 6, y = by & 63;
    const int tid = threadIdx.x;
    const int tx = tid & 15, ty = tid >> 4;
    __shared__ __align__(16) float Ws[16][128];
    __shared__ __align__(16) float Xs[16][64];
    float acc[8][4];
#pragma unroll
    for (int i = 0; i < 8; i++)
#pragma unroll
        for (int j = 0; j < 4; j++) acc[i][j] = 0.f;
    const int l = tid * 4;
    const int kW = l >> 7, coW = l & 127;
    const int kX = l >> 6, pxX = l & 63;
    const float* inrow = in + (size_t)b * Cin * 4096 + (size_t)y * 64;
    for (int c0 = 0; c0 < Cin; c0 += 16) {
        __syncthreads();
        *(float4*)&Ws[kW][coW] =
            *(const float4*)(wp + (size_t)(c0 + kW) * Cout + cout0 + coW);
        *(float4*)&Ws[kW + 8][coW] =
            *(const float4*)(wp + (size_t)(c0 + kW + 8) * Cout + cout0 + coW);
        *(float4*)&Xs[kX][pxX] =
            *(const float4*)(inrow + (size_t)(c0 + kX) * 4096 + pxX);
        __syncthreads();
#pragma unroll
        for (int k = 0; k < 16; k++) {
            const float4 bv = *(const float4*)&Xs[k][tx * 4];
            const float4 a0 = *(const float4*)&Ws[k][ty * 8];
            const float4 a1 = *(const float4*)&Ws[k][ty * 8 + 4];
            const float bj[4] = {bv.x, bv.y, bv.z, bv.w};
            const float ai[8] = {a0.x, a0.y, a0.z, a0.w, a1.x, a1.y, a1.z, a1.w};
#pragma unroll
            for (int i = 0; i < 8; i++)
#pragma unroll
                for (int j = 0; j < 4; j++)
                    acc[i][j] = fmaf(ai[i], bj[j], acc[i][j]);
        }
    }
#pragma unroll
    for (int i = 0; i < 8; i++) {
        const int co = cout0 + ty * 8 + i;
        const float bs = bias[co];
        float* orow = out + (((size_t)b * Cout + co) * 64 + y) * 64;
        float4 cur = *(float4*)(orow + tx * 4);
        cur.x += acc[i][0] + bs; cur.y += acc[i][1] + bs;
        cur.z += acc[i][2] + bs; cur.w += acc[i][3] + bs;
        *(float4*)(orow + tx * 4) = cur;
    }
}

// ------------------------------- VQ ------------------------------------------
__global__ void __launch_bounds__(256)
vq_argmin_k(const float* __restrict__ z, const float* __restrict__ cbT,
            const float* __restrict__ cn, const float* __restrict__ zn,
            unsigned long long* __restrict__ bestkey) {
    const int code0 = blockIdx.x * 64;
    const int by = blockIdx.y;
    const int b = by >> 6, y = by & 63;
    const int tid = threadIdx.x;
    const int tx = tid & 15, ty = tid >> 4;
    __shared__ __align__(16) float Cs[16][64];
    __shared__ __align__(16) float Zs[16][64];
    __shared__ unsigned long long red[16][64];
    float acc[4][4];
#pragma unroll
    for (int i = 0; i < 4; i++)
#pragma unroll
        for (int j = 0; j < 4; j++) acc[i][j] = 0.f;
    const int l = tid * 4;
    const int k = l >> 6, c = l & 63;
    for (int d0 = 0; d0 < 256; d0 += 16) {
        __syncthreads();
        *(float4*)&Cs[k][c] = *(const float4*)&cbT[(size_t)(d0 + k) * 1024 + code0 + c];
        *(float4*)&Zs[k][c] =
            *(const float4*)&z[(((size_t)b * 256 + d0 + k) * 64 + y) * 64 + c];
        __syncthreads();
#pragma unroll
        for (int kk = 0; kk < 16; kk++) {
            const float4 av = *(const float4*)&Cs[kk][ty * 4];
            const float4 bv = *(const float4*)&Zs[kk][tx * 4];
            const float ai[4] = {av.x, av.y, av.z, av.w};
            const float bj[4] = {bv.x, bv.y, bv.z, bv.w};
#pragma unroll
            for (int i = 0; i < 4; i++)
#pragma unroll
                for (int j = 0; j < 4; j++)
                    acc[i][j] = fmaf(ai[i], bj[j], acc[i][j]);
        }
    }
#pragma unroll
    for (int j = 0; j < 4; j++) {
        const float znv = zn[by * 64 + tx * 4 + j];
        unsigned long long best = 0xFFFFFFFFFFFFFFFFull;
#pragma unroll
        for (int i = 0; i < 4; i++) {
            const int code = code0 + ty * 4 + i;
            const float s = (znv - 2.f * acc[i][j]) + cn[code];
            unsigned int u = __float_as_uint(s);
            unsigned int k32 = (u >> 31) ? ~u : (u | 0x80000000u);
            unsigned long long key = ((unsigned long long)k32 << 32) | (unsigned int)code;
            best = (key < best) ? key : best;
        }
        red[ty][tx * 4 + j] = best;
    }
    __syncthreads();
    for (int st = 8; st; st >>= 1) {
        if (ty < st) {
#pragma unroll
            for (int j = 0; j < 4; j++) {
                unsigned long long a = red[ty][tx * 4 + j];
                unsigned long long b2 = red[ty + st][tx * 4 + j];
                red[ty][tx * 4 + j] = (b2 < a) ? b2 : a;
            }
        }
        __syncthreads();
    }
    if (ty == 0) {
#pragma unroll
        for (int j = 0; j < 4; j++)
            atomicMin(&bestkey[by * 64 + tx * 4 + j], red[0][tx * 4 + j]);
    }
}

__global__ void vq_gather_k(const float* __restrict__ z, const float* __restrict__ cb,
                            const unsigned long long* __restrict__ bestkey,
                            float* __restrict__ zq, float* __restrict__ vqsum) {
    const int n = blockIdx.x;
    const int d = threadIdx.x;
    const int idx = (int)(bestkey[n] & 0xFFFFFFFFull);
    const int b = n >> 12, rem = n & 4095;
    const float q = cb[idx * 256 + d];
    const size_t zoff = (((size_t)b * 256 + d) << 12) + rem;
    const float zv = z[zoff];
    const float diff = q - zv;
    zq[zoff] = zv + diff;
    float p = warpReduceSum(diff * diff);
    __shared__ float sh[8];
    if ((threadIdx.x & 31) == 0) sh[threadIdx.x >> 5] = p;
    __syncthreads();
    if (threadIdx.x == 0) {
        float t = 0.f;
#pragma unroll
        for (int i = 0; i < 8; i++) t += sh[i];
        atomicAdd(vqsum, t);
    }
}

// -------------------------------- deconv -------------------------------------
__global__ void deconv_k(const float* __restrict__ in, const float* __restrict__ w,
                         const float* __restrict__ bias, const float* __restrict__ x,
                         float* __restrict__ out, float* __restrict__ reconsum) {
    const int idx = blockIdx.x * blockDim.x + threadIdx.x;
    if (idx >= 393216) return;
    const int ox = idx & 127, oy = (idx >> 7) & 127;
    const int bo = idx >> 14;
    const int o = bo % 3, b = bo / 3;
    float acc = bias[o];
    const int kyp = (oy + 1) & 1, kxp = (ox + 1) & 1;
#pragma unroll
    for (int t = 0; t < 4; t++) {
        const int ky = kyp + 2 * (t >> 1);
        const int kx = kxp + 2 * (t & 1);
        const int ny = oy + 1 - ky, nx = ox + 1 - kx;
        if (ny < 0 || nx < 0) continue;
        const int iy = ny >> 1, ix = nx >> 1;
        if (iy >= 64 || ix >= 64) continue;
        const float* ip = in + (size_t)b * 256 * 4096 + iy * 64 + ix;
        const float* wpp = w + o * 16 + ky * 4 + kx;
        float a = 0.f;
        for (int c2 = 0; c2 < 256; c2++)
            a = fmaf(ip[(size_t)c2 * 4096], wpp[c2 * 48], a);
        acc += a;
    }
    out[idx] = acc;
    const float d = acc - x[idx];
    float p = warpReduceSum(d * d);
    if ((threadIdx.x & 31) == 0) atomicAdd(reconsum, p);
}

__global__ void finalize_k(float* __restrict__ out, const float* __restrict__ vqsum,
                           const float* __restrict__ reconsum) {
    const float recon = *reconsum * (1.f / 393216.f);
    const float vq = 1.25f * (*vqsum) * (1.f / 8388608.f);
    out[393216] = recon + vq;
    out[393217] = recon;
}

// --------------------------------- launch ------------------------------------
extern "C" void kernel_launch(void* const* d_in, const int* in_sizes, int n_in,
                              void* d_out, int out_size) {
    const float* x        = (const float*)d_in[0];
    const float* ec0_w    = (const float*)d_in[1];
    const float* ec0_b    = (const float*)d_in[2];
    const float* ebn0_g   = (const float*)d_in[3];
    const float* ebn0_b   = (const float*)d_in[4];
    const float* ec1_w    = (const float*)d_in[5];
    const float* ec1_b    = (const float*)d_in[6];
    const float* ebn1_g   = (const float*)d_in[7];
    const float* ebn1_b   = (const float*)d_in[8];
    const float* ec2_w    = (const float*)d_in[9];
    const float* ec2_b    = (const float*)d_in[10];
    const float* er_w1    = (const float*)d_in[11];
    const float* er_b1    = (const float*)d_in[12];
    const float* er_w2    = (const float*)d_in[13];
    const float* er_b2    = (const float*)d_in[14];
    const float* ec3_w    = (const float*)d_in[15];
    const float* ec3_b    = (const float*)d_in[16];
    const float* codebook = (const float*)d_in[17];
    const float* dc0_w    = (const float*)d_in[18];
    const float* dc0_b    = (const float*)d_in[19];
    const float* dr_w1    = (const float*)d_in[20];
    const float* dr_b1    = (const float*)d_in[21];
    const float* dr_w2    = (const float*)d_in[22];
    const float* dr_b2    = (const float*)d_in[23];
    const float* dc1_w    = (const float*)d_in[24];
    const float* dc1_b    = (const float*)d_in[25];
    const float* dd_w     = (const float*)d_in[26];
    const float* dd_b     = (const float*)d_in[27];
    float* out = (float*)d_out;

    float *bufA, *bufB, *bufT, *bufZ, *V, *M, *pwE2, *pwDr2;
    float *uh1, *ul1, *uh2, *ul2, *uh3, *ul3, *uhE, *ulE;
    float *uhD0, *ulD0, *uhD1, *ulD1, *uhDr, *ulDr;
    float *cbT, *cn, *zn, *bnsc, *bnsh, *vqsum, *reconsum;
    unsigned long long* bestkey;
    cudaGetSymbolAddress((void**)&bufA, g_bufA);
    cudaGetSymbolAddress((void**)&bufB, g_bufB);
    cudaGetSymbolAddress((void**)&bufT, g_bufT);
    cudaGetSymbolAddress((void**)&bufZ, g_bufZ);
    cudaGetSymbolAddress((void**)&V, g_V);
    cudaGetSymbolAddress((void**)&M, g_M);
    cudaGetSymbolAddress((void**)&uh1, g_uh1);  cudaGetSymbolAddress((void**)&ul1, g_ul1);
    cudaGetSymbolAddress((void**)&uh2, g_uh2);  cudaGetSymbolAddress((void**)&ul2, g_ul2);
    cudaGetSymbolAddress((void**)&uh3, g_uh3);  cudaGetSymbolAddress((void**)&ul3, g_ul3);
    cudaGetSymbolAddress((void**)&uhE, g_uhE);  cudaGetSymbolAddress((void**)&ulE, g_ulE);
    cudaGetSymbolAddress((void**)&uhD0, g_uhD0); cudaGetSymbolAddress((void**)&ulD0, g_ulD0);
    cudaGetSymbolAddress((void**)&uhD1, g_uhD1); cudaGetSymbolAddress((void**)&ulD1, g_ulD1);
    cudaGetSymbolAddress((void**)&uhDr, g_uhDr); cudaGetSymbolAddress((void**)&ulDr, g_ulDr);
    cudaGetSymbolAddress((void**)&pwE2, g_pwE2);
    cudaGetSymbolAddress((void**)&pwDr2, g_pwDr2);
    cudaGetSymbolAddress((void**)&cbT, g_cbT);
    cudaGetSymbolAddress((void**)&cn, g_cnorm);
    cudaGetSymbolAddress((void**)&zn, g_znorm);
    cudaGetSymbolAddress((void**)&bnsc, g_bnscale);
    cudaGetSymbolAddress((void**)&bnsh, g_bnshift);
    cudaGetSymbolAddress((void**)&vqsum, g_vqsum);
    cudaGetSymbolAddress((void**)&reconsum, g_reconsum);
    cudaGetSymbolAddress((void**)&bestkey, g_bestkey);

    const int SMEM = (4096 + 4096 + 4352 + 4352) * 4;   // 67584 B
    cudaFuncSetAttribute(win_gemm_tf_k, cudaFuncAttributeMaxDynamicSharedMemorySize, SMEM);

    const size_t resStride = (size_t)36 * 512 * 128;    // per res layer elems

    // ---- weight prep ----
    wtrans4f_k<<<512, 256>>>(ec1_w, uh1, ul1, 1, 256, 512);
    wtrans4f_k<<<1024, 256>>>(ec2_w, uh2, ul2, 1, 512, 512);
    wtrans4f_k<<<512, 256>>>(ec3_w, uh3, ul3, 1, 512, 256);
    wtrans4f_k<<<4096, 256>>>(er_w1, uhE, ulE, 16, 512, 128);
    wtrans4f_k<<<512, 256>>>(dc0_w, uhD0, ulD0, 1, 256, 512);
    wtrans4f_k<<<512, 256>>>(dc1_w, uhD1, ulD1, 1, 512, 256);
    wtrans4f_k<<<4096, 256>>>(dr_w1, uhDr, ulDr, 16, 512, 128);
    pack1x1_k<<<2048, 256>>>(er_w2, pwE2, 16, 128, 512);
    pack1x1_k<<<2048, 256>>>(dr_w2, pwDr2, 16, 128, 512);
    packT_k<<<1024, 256>>>(codebook, cbT);
    init_k<<<128, 256>>>(bestkey, vqsum, reconsum);
    cnorm_k<<<1024, 256>>>(codebook, cn);

    // ---- encoder ----
    conv0_k<<<32768, 256>>>(x, ec0_w, ec0_b, bufZ);
    bn_stats_k<<<256, 256>>>(bufZ, ebn0_g, ebn0_b, 256, bnsc, bnsh);
    bn_apply_k<<<32768, 256>>>(bufZ, bnsc, bnsh, 256, 8 * 256 * 4096);

    win4_in_k<false><<<2048, 256>>>(bufZ, V, 256);
    win_gemm_tf_k<<<dim3(144, 16), 256, SMEM>>>(uh1, ul1, V, M, 256, 512);
    win4_out_k<false><<<4096, 256>>>(M, ec1_b, bufA, 512);
    bn_stats_k<<<512, 256>>>(bufA, ebn1_g, ebn1_b, 512, bnsc, bnsh);
    bn_apply_k<<<65536, 256>>>(bufA, bnsc, bnsh, 512, 8 * 512 * 4096);

    win4_in_k<false><<<4096, 256>>>(bufA, V, 512);
    win_gemm_tf_k<<<dim3(144, 16), 256, SMEM>>>(uh2, ul2, V, M, 512, 512);
    win4_out_k<false><<<4096, 256>>>(M, ec2_b, bufB, 512);

    for (int blk = 0; blk < 16; blk++) {
        win4_in_k<true><<<4096, 256>>>(bufB, V, 512);
        win_gemm_tf_k<<<dim3(36, 16), 256, SMEM>>>(
            uhE + blk * resStride, ulE + blk * resStride, V, M, 512, 128);
        win4_out_k<true><<<1024, 256>>>(M, er_b1 + blk * 128, bufT, 128);
        conv1x1_acc_k<<<dim3(4, BH), 256>>>(
            bufT, pwE2 + (size_t)blk * 128 * 512, er_b2 + blk * 512, bufB, 128, 512);
        if ((blk & 3) == 3)
            relu_ip_k<<<65536, 256>>>(bufB, 8 * 512 * 4096);
    }

    win4_in_k<false><<<4096, 256>>>(bufB, V, 512);
    win_gemm_tf_k<<<dim3(72, 16), 256, SMEM>>>(uh3, ul3, V, M, 512, 256);
    win4_out_k<false><<<2048, 256>>>(M, ec3_b, bufZ, 256);

    // ---- vector quantizer ----
    znorm_k<<<128, 256>>>(bufZ, zn);
    vq_argmin_k<<<dim3(16, BH), 256>>>(bufZ, cbT, cn, zn, bestkey);
    vq_gather_k<<<32768, 256>>>(bufZ, codebook, bestkey, bufA, vqsum);

    // ---- decoder ----
    win4_in_k<false><<<2048, 256>>>(bufA, V, 256);
    win_gemm_tf_k<<<dim3(144, 16), 256, SMEM>>>(uhD0, ulD0, V, M, 256, 512);
    win4_out_k<false><<<4096, 256>>>(M, dc0_b, bufB, 512);

    for (int blk = 0; blk < 16; blk++) {
        win4_in_k<true><<<4096, 256>>>(bufB, V, 512);
        win_gemm_tf_k<<<dim3(36, 16), 256, SMEM>>>(
            uhDr + blk * resStride, ulDr + blk * resStride, V, M, 512, 128);
        win4_out_k<true><<<1024, 256>>>(M, dr_b1 + blk * 128, bufT, 128);
        conv1x1_acc_k<<<dim3(4, BH), 256>>>(
            bufT, pwDr2 + (size_t)blk * 128 * 512, dr_b2 + blk * 512, bufB, 128, 512);
        if ((blk & 3) == 3)
            relu_ip_k<<<65536, 256>>>(bufB, 8 * 512 * 4096);
    }

    win4_in_k<false><<<4096, 256>>>(bufB, V, 512);
    win_gemm_tf_k<<<dim3(72, 16), 256, SMEM>>>(uhD1, ulD1, V, M, 512, 256);
    win4_out_k<true><<<2048, 256>>>(M, dc1_b, bufZ, 256);

    deconv_k<<<1536, 256>>>(bufZ, dd_w, dd_b, x, out, reconsum);
    finalize_k<<<1, 1>>>(out, vqsum, reconsum);
}